// round 7
// baseline (speedup 1.0000x reference)
#include <cuda_runtime.h>
#include <math.h>

// Problem constants
#define B 8
#define L 256
#define D 16
#define H 128
#define DFF 128
#define EPSV 1e-6f

#define TI 8        // query rows per block
#define RI 4        // i-rows per thread

typedef unsigned long long u64;

// Scratch (device globals)
__device__ float g_v  [B * L * D];
__device__ float g_qa [B * L * H];
__device__ float g_qb [B * L * H];
__device__ float2 g_kbT[B * (H/2) * L];   // [b][hp][j] -> (kb[2hp], kb[2hp+1])
__device__ float2 g_kaT[B * (H/2) * L];

// ---------------- packed f32x2 helpers ----------------
__device__ __forceinline__ u64 add2(u64 a, u64 b) {
    u64 d; asm("add.rn.f32x2 %0,%1,%2;" : "=l"(d) : "l"(a), "l"(b)); return d;
}
__device__ __forceinline__ u64 fma2(u64 a, u64 b, u64 c) {
    u64 d; asm("fma.rn.f32x2 %0,%1,%2,%3;" : "=l"(d) : "l"(a), "l"(b), "l"(c)); return d;
}
__device__ __forceinline__ u64 relu2(u64 v) {
    float lo, hi;
    asm("mov.b64 {%0,%1}, %2;" : "=f"(lo), "=f"(hi) : "l"(v));
    lo = fmaxf(lo, 0.f); hi = fmaxf(hi, 0.f);
    u64 d; asm("mov.b64 %0,{%1,%2};" : "=l"(d) : "f"(lo), "f"(hi)); return d;
}
__device__ __forceinline__ float redu2(u64 v) {
    float lo, hi;
    asm("mov.b64 {%0,%1}, %2;" : "=f"(lo), "=f"(hi) : "l"(v));
    return lo + hi;
}
__device__ __forceinline__ void cpa16(void* dst_smem, const void* src_gmem) {
    unsigned d = (unsigned)__cvta_generic_to_shared(dst_smem);
    asm volatile("cp.async.cg.shared.global [%0], [%1], 16;" :: "r"(d), "l"(src_gmem) : "memory");
}

// ---------------------------------------------------------------------------
// Kernel 1: projections + MLP pre-activations; kb/ka stored transposed+packed
// ---------------------------------------------------------------------------
__global__ __launch_bounds__(128) void k_precompute(
    const float* __restrict__ x,
    const float* __restrict__ wq, const float* __restrict__ bq,
    const float* __restrict__ wk, const float* __restrict__ bk,
    const float* __restrict__ wv, const float* __restrict__ bv,
    const float* __restrict__ nn_w1, const float* __restrict__ nn_b1)
{
    __shared__ float xs[D], qs[D], ks[D];
    const int row = blockIdx.x;          // b*256 + l
    const int bb = row >> 8, l = row & 255;
    const int t = threadIdx.x;

    if (t < D) xs[t] = x[row * D + t];
    __syncthreads();

    if (t < D) {
        float a = bq[t];
        #pragma unroll
        for (int d = 0; d < D; ++d) a = fmaf(xs[d], wq[d * D + t], a);
        qs[t] = a;
    } else if (t < 2 * D) {
        const int c = t - D;
        float a = bk[c];
        #pragma unroll
        for (int d = 0; d < D; ++d) a = fmaf(xs[d], wk[d * D + c], a);
        ks[c] = a;
    } else if (t < 3 * D) {
        const int c = t - 2 * D;
        float a = bv[c];
        #pragma unroll
        for (int d = 0; d < D; ++d) a = fmaf(xs[d], wv[d * D + c], a);
        g_v[row * D + c] = a;
    }
    __syncthreads();

    const int h = t;  // 0..127
    float qa = 0.f, qb = 0.f;
    float kb = nn_b1[h], ka = nn_b1[h];
    #pragma unroll
    for (int d = 0; d < D; ++d) {
        const float w1q = nn_w1[d * H + h];
        const float w1k = nn_w1[(d + D) * H + h];
        qa = fmaf(qs[d], w1q, qa);
        qb = fmaf(qs[d], w1k, qb);
        kb = fmaf(ks[d], w1k, kb);
        ka = fmaf(ks[d], w1q, ka);
    }
    g_qa[row * H + h] = qa;
    g_qb[row * H + h] = qb;

    const float kb_o = __shfl_xor_sync(0xffffffffu, kb, 1);
    const float ka_o = __shfl_xor_sync(0xffffffffu, ka, 1);
    if (!(t & 1)) {
        const int hp = t >> 1;
        g_kbT[(bb * (H/2) + hp) * L + l] = make_float2(kb, kb_o);
        g_kaT[(bb * (H/2) + hp) * L + l] = make_float2(ka, ka_o);
    }
}

// ---------------------------------------------------------------------------
// Kernel 2: fused. 256 blocks x 512 threads, 2 CTAs/SM (32 warps/SM).
// ---------------------------------------------------------------------------
struct __align__(16) Smem {
    float qa[TI * 132];
    float qb[TI * 132];
    float logits[TI * L];
    float maskS[TI * L];     // aliased after phase 2: ctxp/fp/hidden
    float vT[D * 260];
    float w2[H];
    float wo[D * D];
    float f1[D * DFF];
    float f2T[D * 132];
    float xr[TI * D];
    float out1[TI * D];
    float f1b[DFF];
    float bo[D], f2b[D];
    float g1[D], be1[D], g2[D], be2[D];
};

__global__ __launch_bounds__(512, 2) void k_main(
    const float* __restrict__ x,
    const float* __restrict__ mask,
    const float* __restrict__ wo_g, const float* __restrict__ bo_g,
    const float* __restrict__ w2_g, const float* __restrict__ b2_g,
    const float* __restrict__ f1_g, const float* __restrict__ f1b_g,
    const float* __restrict__ f2_g, const float* __restrict__ f2b_g,
    const float* __restrict__ g1_g, const float* __restrict__ be1_g,
    const float* __restrict__ g2_g, const float* __restrict__ be2_g,
    float* __restrict__ out)
{
    extern __shared__ char smem_raw[];
    Smem* s = reinterpret_cast<Smem*>(smem_raw);

    const int tid   = threadIdx.x;
    const int b     = blockIdx.x >> 5;          // 32 blocks per batch
    const int iBase = (blockIdx.x & 31) << 3;   // 8 rows per block

    // ---- mask cp.async immediately (consumed only at phase 2) ----
    {
        const float4* gm = reinterpret_cast<const float4*>(mask + (size_t)(b * L + iBase) * L);
        float4* sm = reinterpret_cast<float4*>(s->maskS);
        cpa16(sm + tid, gm + tid);              // 512 f4 = 2048 floats
        asm volatile("cp.async.commit_group;" ::: "memory");
    }

    // ---------------- Phase 0: cooperative smem fills ----------------
    {
        if (tid < 256) {
            const int ir = tid >> 5, h4 = tid & 31;    // 8 rows x 32 f4
            const float4* gqa = reinterpret_cast<const float4*>(g_qa + (b * L + iBase) * H);
            const float4* gqb = reinterpret_cast<const float4*>(g_qb + (b * L + iBase) * H);
            reinterpret_cast<float4*>(s->qa)[ir * 33 + h4] = gqa[tid];
            reinterpret_cast<float4*>(s->qb)[ir * 33 + h4] = gqb[tid];
        }
        // vT: transpose v[j][d] -> vT[d][260]
        const float4* gv = reinterpret_cast<const float4*>(g_v + b * L * D);
        #pragma unroll
        for (int r = 0; r < 2; ++r) {
            const int e = tid + 512 * r;               // < 1024
            const float4 val = gv[e];
            const int j = e >> 2, dq = e & 3;
            s->vT[(dq * 4 + 0) * 260 + j] = val.x;
            s->vT[(dq * 4 + 1) * 260 + j] = val.y;
            s->vT[(dq * 4 + 2) * 260 + j] = val.z;
            s->vT[(dq * 4 + 3) * 260 + j] = val.w;
        }
        // f2T: transpose f2[h][d] -> f2T[d][132]
        #pragma unroll
        for (int r = 0; r < 4; ++r) {
            const int e = tid + 512 * r;               // < 2048
            const int h = e >> 4, d = e & 15;
            s->f2T[d * 132 + h] = f2_g[e];
        }
        reinterpret_cast<float4*>(s->f1)[tid] = reinterpret_cast<const float4*>(f1_g)[tid];
        if (tid < H)   { s->w2[tid] = w2_g[tid]; s->f1b[tid] = f1b_g[tid]; }
        if (tid < 256) s->wo[tid] = wo_g[tid];
        if (tid < 128) s->xr[tid] = x[(b * L + iBase) * D + tid];
        if (tid < D) {
            s->bo[tid]  = bo_g[tid];  s->f2b[tid] = f2b_g[tid];
            s->g1[tid]  = g1_g[tid];  s->be1[tid] = be1_g[tid];
            s->g2[tid]  = g2_g[tid];  s->be2[tid] = be2_g[tid];
        }
    }
    const float b2x2 = 2.f * b2_g[0];
    __syncthreads();

    // ---------------- Phase 1: pairwise-MLP logits (barrier-free) ----------
    const int j = tid & 255;       // fixed key column
    const int g = tid >> 8;        // 0/1 -> i-rows 0-3 / 4-7

    const u64* gkb = reinterpret_cast<const u64*>(g_kbT + b * (H/2) * L) + j;   // stride L per hp
    const u64* gka = reinterpret_cast<const u64*>(g_kaT + b * (H/2) * L) + j;
    const ulonglong2* qaB = reinterpret_cast<const ulonglong2*>(s->qa) + (g * RI) * 33;
    const ulonglong2* qbB = reinterpret_cast<const ulonglong2*>(s->qb) + (g * RI) * 33;
    const ulonglong2* w2p = reinterpret_cast<const ulonglong2*>(s->w2);

    u64 acc[RI];
    #pragma unroll
    for (int r = 0; r < RI; ++r) acc[r] = 0ull;

    u64 KC0 = gkb[0], KC1 = gkb[L];
    u64 AC0 = gka[0], AC1 = gka[L];

    #pragma unroll 8
    for (int c = 0; c < 32; ++c) {        // 32 chunks of 4 h (2 hp)
        u64 KN0, KN1, AN0, AN1;
        if (c < 31) {
            KN0 = gkb[(2 * c + 2) * L];
            KN1 = gkb[(2 * c + 3) * L];
            AN0 = gka[(2 * c + 2) * L];
            AN1 = gka[(2 * c + 3) * L];
        }
        const ulonglong2 W = w2p[c];
        #pragma unroll
        for (int r = 0; r < RI; ++r) {
            const ulonglong2 a  = qaB[r * 33 + c];
            const ulonglong2 bb = qbB[r * 33 + c];
            acc[r] = fma2(add2(relu2(add2(a.x, KC0)), relu2(add2(bb.x, AC0))), W.x, acc[r]);
            acc[r] = fma2(add2(relu2(add2(a.y, KC1)), relu2(add2(bb.y, AC1))), W.y, acc[r]);
        }
        KC0 = KN0; KC1 = KN1; AC0 = AN0; AC1 = AN1;
    }

    #pragma unroll
    for (int r = 0; r < RI; ++r)
        s->logits[(g * RI + r) * L + j] = redu2(acc[r]);

    asm volatile("cp.async.wait_group 0;" ::: "memory");
    __syncthreads();

    // ---------------- Phase 2: softmax (8 warps x 8 rows) ------------------
    if (tid < 256) {
        const int warp = tid >> 5, lane = tid & 31;
        const int r = warp;           // 8 rows
        float vals[8];
        float mx = -INFINITY;
        #pragma unroll
        for (int t = 0; t < 8; ++t) {
            const int jj = lane + 32 * t;
            const float lg = s->logits[r * L + jj] + b2x2 + s->maskS[r * L + jj] * (-1e9f);
            vals[t] = lg;
            mx = fmaxf(mx, lg);
        }
        #pragma unroll
        for (int m = 16; m > 0; m >>= 1)
            mx = fmaxf(mx, __shfl_xor_sync(0xffffffffu, mx, m));
        float sum = 0.f;
        #pragma unroll
        for (int t = 0; t < 8; ++t) { vals[t] = __expf(vals[t] - mx); sum += vals[t]; }
        #pragma unroll
        for (int m = 16; m > 0; m >>= 1)
            sum += __shfl_xor_sync(0xffffffffu, sum, m);
        const float inv = 1.f / sum;
        #pragma unroll
        for (int t = 0; t < 8; ++t)
            s->logits[r * L + lane + 32 * t] = vals[t] * inv;
    }
    __syncthreads();

    // aliased scratch in maskS (mask no longer needed): 512 + 512 + 1024 = 2048
    float* ctxp   = s->maskS;            // 4 x 128
    float* fp     = s->maskS + 512;      // 4 x 128
    float* hidden = s->maskS + 1024;     // 8 x 128

    // ---------------- Phase 3: ctx = attn @ v (4 j-quarters) ---------------
    {
        const int p  = tid & 127;
        const int hf = tid >> 7;          // 0..3
        const int il = p >> 4, dl = p & 15;
        const float4* arow = reinterpret_cast<const float4*>(s->logits + il * L + hf * 64);
        const float4* vrow = reinterpret_cast<const float4*>(s->vT + dl * 260 + hf * 64);
        float c = 0.f;
        #pragma unroll
        for (int q = 0; q < 16; ++q) {
            const float4 a4 = arow[q];
            const float4 v4 = vrow[q];
            c = fmaf(a4.x, v4.x, c);
            c = fmaf(a4.y, v4.y, c);
            c = fmaf(a4.z, v4.z, c);
            c = fmaf(a4.w, v4.w, c);
        }
        ctxp[hf * 128 + p] = c;
    }
    __syncthreads();

    // attn_out + residual + LN1 (first 128 threads)
    if (tid < 128) {
        const int il = tid >> 4, dl = tid & 15;
        float ao = s->bo[dl];
        #pragma unroll
        for (int e = 0; e < D; ++e) {
            const float cs = ctxp[il * D + e] + ctxp[128 + il * D + e]
                           + ctxp[256 + il * D + e] + ctxp[384 + il * D + e];
            ao = fmaf(cs, s->wo[e * D + dl], ao);
        }
        const float hval = s->xr[tid] + ao;   // RES=1
        float m = hval, sq = hval * hval;
        #pragma unroll
        for (int msk = 8; msk > 0; msk >>= 1) {
            m  += __shfl_xor_sync(0xffffffffu, m,  msk);
            sq += __shfl_xor_sync(0xffffffffu, sq, msk);
        }
        m *= (1.f / 16.f);
        const float var = sq * (1.f / 16.f) - m * m;
        s->out1[tid] = (hval - m) * rsqrtf(var + EPSV) * s->g1[dl] + s->be1[dl];
    }
    __syncthreads();

    // ---------------- Phase 4: FFN hidden (512 threads, 2 i's each) --------
    {
        const int h   = tid & 127;
        const int ig2 = tid >> 7;     // 0..3
        #pragma unroll
        for (int cc = 0; cc < 2; ++cc) {
            const int il = ig2 * 2 + cc;
            float a2 = s->f1b[h];
            #pragma unroll
            for (int d = 0; d < D; ++d)
                a2 = fmaf(s->out1[il * D + d], s->f1[d * DFF + h], a2);
            hidden[il * DFF + h] = fmaxf(a2, 0.f);
        }
    }
    __syncthreads();

    // f2 contraction (f2T, float4), 4 h-quarters
    {
        const int p  = tid & 127;
        const int hf = tid >> 7;
        const int il = p >> 4, dl = p & 15;
        const float4* hrow = reinterpret_cast<const float4*>(hidden + il * DFF + hf * 32);
        const float4* frow = reinterpret_cast<const float4*>(s->f2T + dl * 132 + hf * 32);
        float f = 0.f;
        #pragma unroll
        for (int q = 0; q < 8; ++q) {
            const float4 h4 = hrow[q];
            const float4 f4 = frow[q];
            f = fmaf(h4.x, f4.x, f);
            f = fmaf(h4.y, f4.y, f);
            f = fmaf(h4.z, f4.z, f);
            f = fmaf(h4.w, f4.w, f);
        }
        fp[hf * 128 + p] = f;
    }
    __syncthreads();

    if (tid < 128) {
        const int il = tid >> 4, dl = tid & 15;
        const float f = s->f2b[dl] + fp[tid] + fp[128 + tid] + fp[256 + tid] + fp[384 + tid];
        const float hval = s->out1[tid] + f;   // RES=1
        float m = hval, sq = hval * hval;
        #pragma unroll
        for (int msk = 8; msk > 0; msk >>= 1) {
            m  += __shfl_xor_sync(0xffffffffu, m,  msk);
            sq += __shfl_xor_sync(0xffffffffu, sq, msk);
        }
        m *= (1.f / 16.f);
        const float var = sq * (1.f / 16.f) - m * m;
        const float o = (hval - m) * rsqrtf(var + EPSV) * s->g2[dl] + s->be2[dl];
        out[(size_t)(b * L + iBase + il) * D + dl] = o;
    }
}

// ---------------------------------------------------------------------------
extern "C" void kernel_launch(void* const* d_in, const int* in_sizes, int n_in,
                              void* d_out, int out_size)
{
    const float* x     = (const float*)d_in[0];
    const float* mask  = (const float*)d_in[1];
    const float* wq    = (const float*)d_in[2];
    const float* bq    = (const float*)d_in[3];
    const float* wk    = (const float*)d_in[4];
    const float* bk    = (const float*)d_in[5];
    const float* wv    = (const float*)d_in[6];
    const float* bv    = (const float*)d_in[7];
    const float* wo    = (const float*)d_in[8];
    const float* bo    = (const float*)d_in[9];
    const float* nn_w1 = (const float*)d_in[10];
    const float* nn_b1 = (const float*)d_in[11];
    const float* nn_w2 = (const float*)d_in[12];
    const float* nn_b2 = (const float*)d_in[13];
    const float* f1    = (const float*)d_in[14];
    const float* f1b   = (const float*)d_in[15];
    const float* f2    = (const float*)d_in[16];
    const float* f2b   = (const float*)d_in[17];
    const float* g1    = (const float*)d_in[18];
    const float* be1   = (const float*)d_in[19];
    const float* g2    = (const float*)d_in[20];
    const float* be2   = (const float*)d_in[21];
    float* out = (float*)d_out;

    cudaFuncSetAttribute(k_main, cudaFuncAttributeMaxDynamicSharedMemorySize,
                         (int)sizeof(Smem));

    k_precompute<<<B * L, 128>>>(x, wq, bq, wk, bk, wv, bv, nn_w1, nn_b1);
    k_main<<<B * (L / TI), 512, sizeof(Smem)>>>(
        x, mask, wo, bo, nn_w2, nn_b2, f1, f1b, f2, f2b, g1, be1, g2, be2, out);
}

// round 8
// speedup vs baseline: 1.1293x; 1.1293x over previous
#include <cuda_runtime.h>
#include <math.h>

// Problem constants
#define B 8
#define L 256
#define D 16
#define H 128
#define DFF 128
#define EPSV 1e-6f

#define TI 16       // query rows per block
#define RI 8        // i-rows per thread

typedef unsigned long long u64;

// Scratch (device globals)
__device__ float  g_v   [B * L * D];
__device__ float  g_qa  [B * L * H];
__device__ float  g_qb  [B * L * H];
__device__ float4 g_kbaT[B * (H/2) * L];  // [b][hp][j] = (kb[2hp],kb[2hp+1],ka[2hp],ka[2hp+1])

// ---------------- packed f32x2 helpers ----------------
__device__ __forceinline__ u64 add2(u64 a, u64 b) {
    u64 d; asm("add.rn.f32x2 %0,%1,%2;" : "=l"(d) : "l"(a), "l"(b)); return d;
}
__device__ __forceinline__ u64 fma2(u64 a, u64 b, u64 c) {
    u64 d; asm("fma.rn.f32x2 %0,%1,%2,%3;" : "=l"(d) : "l"(a), "l"(b), "l"(c)); return d;
}
__device__ __forceinline__ u64 relu2(u64 v) {
    float lo, hi;
    asm("mov.b64 {%0,%1}, %2;" : "=f"(lo), "=f"(hi) : "l"(v));
    lo = fmaxf(lo, 0.f); hi = fmaxf(hi, 0.f);
    u64 d; asm("mov.b64 %0,{%1,%2};" : "=l"(d) : "f"(lo), "f"(hi)); return d;
}
__device__ __forceinline__ float redu2(u64 v) {
    float lo, hi;
    asm("mov.b64 {%0,%1}, %2;" : "=f"(lo), "=f"(hi) : "l"(v));
    return lo + hi;
}
__device__ __forceinline__ void cpa16(void* dst_smem, const void* src_gmem) {
    unsigned d = (unsigned)__cvta_generic_to_shared(dst_smem);
    asm volatile("cp.async.cg.shared.global [%0], [%1], 16;" :: "r"(d), "l"(src_gmem) : "memory");
}

// ---------------------------------------------------------------------------
// Kernel 1: projections + MLP pre-activations; kb/ka interleaved transposed
// ---------------------------------------------------------------------------
__global__ __launch_bounds__(128) void k_precompute(
    const float* __restrict__ x,
    const float* __restrict__ wq, const float* __restrict__ bq,
    const float* __restrict__ wk, const float* __restrict__ bk,
    const float* __restrict__ wv, const float* __restrict__ bv,
    const float* __restrict__ nn_w1, const float* __restrict__ nn_b1)
{
    __shared__ float xs[D], qs[D], ks[D];
    const int row = blockIdx.x;          // b*256 + l
    const int bb = row >> 8, l = row & 255;
    const int t = threadIdx.x;

    if (t < D) xs[t] = x[row * D + t];
    __syncthreads();

    if (t < D) {
        float a = bq[t];
        #pragma unroll
        for (int d = 0; d < D; ++d) a = fmaf(xs[d], wq[d * D + t], a);
        qs[t] = a;
    } else if (t < 2 * D) {
        const int c = t - D;
        float a = bk[c];
        #pragma unroll
        for (int d = 0; d < D; ++d) a = fmaf(xs[d], wk[d * D + c], a);
        ks[c] = a;
    } else if (t < 3 * D) {
        const int c = t - 2 * D;
        float a = bv[c];
        #pragma unroll
        for (int d = 0; d < D; ++d) a = fmaf(xs[d], wv[d * D + c], a);
        g_v[row * D + c] = a;
    }
    __syncthreads();

    const int h = t;  // 0..127
    float qa = 0.f, qb = 0.f;
    float kb = nn_b1[h], ka = nn_b1[h];
    #pragma unroll
    for (int d = 0; d < D; ++d) {
        const float w1q = nn_w1[d * H + h];
        const float w1k = nn_w1[(d + D) * H + h];
        qa = fmaf(qs[d], w1q, qa);
        qb = fmaf(qs[d], w1k, qb);
        kb = fmaf(ks[d], w1k, kb);
        ka = fmaf(ks[d], w1q, ka);
    }
    g_qa[row * H + h] = qa;
    g_qb[row * H + h] = qb;

    const float kb_o = __shfl_xor_sync(0xffffffffu, kb, 1);
    const float ka_o = __shfl_xor_sync(0xffffffffu, ka, 1);
    if (!(t & 1)) {
        const int hp = t >> 1;
        g_kbaT[(bb * (H/2) + hp) * L + l] = make_float4(kb, kb_o, ka, ka_o);
    }
}

// ---------------------------------------------------------------------------
// Kernel 2: fused. 128 blocks x 1024 threads (1 CTA/SM, 32 warps/SM).
// Thread = (j, i-half g, h-half hh). Partial logits summed in softmax.
// ---------------------------------------------------------------------------
struct __align__(16) Smem {
    float qa[TI * 132];          // 2112
    float qb[TI * 132];          // 2112
    float logitsP[2][TI * L];    // 8192 ; [0] holds softmax result; [1] -> hidden later
    float maskS[TI * L];         // 4096 ; aliased after phase 2: ctxp/fp/csum
    float vT[D * 260];           // 4160
    float w2[H];
    float wo[D * D];
    float f1[D * DFF];
    float f2T[D * 132];
    float xr[TI * D];
    float out1[TI * D];
    float f1b[DFF];
    float bo[D], f2b[D];
    float g1[D], be1[D], g2[D], be2[D];
};

__global__ __launch_bounds__(1024, 1) void k_main(
    const float* __restrict__ x,
    const float* __restrict__ mask,
    const float* __restrict__ wo_g, const float* __restrict__ bo_g,
    const float* __restrict__ w2_g, const float* __restrict__ b2_g,
    const float* __restrict__ f1_g, const float* __restrict__ f1b_g,
    const float* __restrict__ f2_g, const float* __restrict__ f2b_g,
    const float* __restrict__ g1_g, const float* __restrict__ be1_g,
    const float* __restrict__ g2_g, const float* __restrict__ be2_g,
    float* __restrict__ out)
{
    extern __shared__ char smem_raw[];
    Smem* s = reinterpret_cast<Smem*>(smem_raw);

    const int tid   = threadIdx.x;
    const int b     = blockIdx.x >> 4;
    const int iBase = (blockIdx.x & 15) << 4;

    // ---- mask cp.async immediately (consumed only at phase 2) ----
    {
        const float4* gm = reinterpret_cast<const float4*>(mask + (size_t)(b * L + iBase) * L);
        cpa16(reinterpret_cast<float4*>(s->maskS) + tid, gm + tid);   // 1024 f4
        asm volatile("cp.async.commit_group;" ::: "memory");
    }

    // ---------------- Phase 0: cooperative smem fills ----------------
    {
        if (tid < 512) {
            const int ir = tid >> 5, h4 = tid & 31;    // 16 rows x 32 f4
            const float4* gqa = reinterpret_cast<const float4*>(g_qa + (b * L + iBase) * H);
            const float4* gqb = reinterpret_cast<const float4*>(g_qb + (b * L + iBase) * H);
            reinterpret_cast<float4*>(s->qa)[ir * 33 + h4] = gqa[tid];
            reinterpret_cast<float4*>(s->qb)[ir * 33 + h4] = gqb[tid];
        }
        // vT: transpose v[j][d] -> vT[d][260]
        const float4* gv = reinterpret_cast<const float4*>(g_v + b * L * D);
        {
            const float4 val = gv[tid];                // 1024 f4
            const int j = tid >> 2, dq = tid & 3;
            s->vT[(dq * 4 + 0) * 260 + j] = val.x;
            s->vT[(dq * 4 + 1) * 260 + j] = val.y;
            s->vT[(dq * 4 + 2) * 260 + j] = val.z;
            s->vT[(dq * 4 + 3) * 260 + j] = val.w;
        }
        // f2T: transpose f2[h][d] -> f2T[d][132]
        #pragma unroll
        for (int r = 0; r < 2; ++r) {
            const int e = tid + 1024 * r;              // < 2048
            const int h = e >> 4, d = e & 15;
            s->f2T[d * 132 + h] = f2_g[e];
        }
        if (tid < 512)
            reinterpret_cast<float4*>(s->f1)[tid] = reinterpret_cast<const float4*>(f1_g)[tid];
        if (tid < H)   { s->w2[tid] = w2_g[tid]; s->f1b[tid] = f1b_g[tid]; }
        if (tid < 256) {
            s->wo[tid] = wo_g[tid];
            s->xr[tid] = x[(b * L + iBase) * D + tid];
        }
        if (tid < D) {
            s->bo[tid]  = bo_g[tid];  s->f2b[tid] = f2b_g[tid];
            s->g1[tid]  = g1_g[tid];  s->be1[tid] = be1_g[tid];
            s->g2[tid]  = g2_g[tid];  s->be2[tid] = be2_g[tid];
        }
    }
    const float b2x2 = 2.f * b2_g[0];
    __syncthreads();

    // ---------------- Phase 1: pairwise-MLP logits (barrier-free) ----------
    const int j  = tid & 255;          // fixed key column
    const int g  = (tid >> 8) & 1;     // i-half: rows g*8 .. g*8+7
    const int hh = tid >> 9;           // h-half: hp in [hh*32, hh*32+32)

    // interleaved kba: element (u64 K pair, u64 A pair), stride L per hp
    const ulonglong2* gkba = reinterpret_cast<const ulonglong2*>(g_kbaT)
                             + (size_t)(b * (H/2) + hh * 32) * L + j;
    const ulonglong2* qaB = reinterpret_cast<const ulonglong2*>(s->qa) + (g * RI) * 33 + hh * 16;
    const ulonglong2* qbB = reinterpret_cast<const ulonglong2*>(s->qb) + (g * RI) * 33 + hh * 16;
    const ulonglong2* w2p = reinterpret_cast<const ulonglong2*>(s->w2) + hh * 16;

    u64 acc[RI];
    #pragma unroll
    for (int r = 0; r < RI; ++r) acc[r] = 0ull;

    ulonglong2 C0 = gkba[0];        // hp0: (K,A)
    ulonglong2 C1 = gkba[L];        // hp1

    #pragma unroll 4
    for (int c = 0; c < 16; ++c) {     // 16 chunks of 4 h (2 hp)
        ulonglong2 N0, N1;
        if (c < 15) {
            N0 = gkba[(2 * c + 2) * L];
            N1 = gkba[(2 * c + 3) * L];
        }
        const ulonglong2 W = w2p[c];
        #pragma unroll
        for (int r = 0; r < RI; ++r) {
            const ulonglong2 a  = qaB[r * 33 + c];
            const ulonglong2 bb = qbB[r * 33 + c];
            acc[r] = fma2(add2(relu2(add2(a.x, C0.x)), relu2(add2(bb.x, C0.y))), W.x, acc[r]);
            acc[r] = fma2(add2(relu2(add2(a.y, C1.x)), relu2(add2(bb.y, C1.y))), W.y, acc[r]);
        }
        C0 = N0; C1 = N1;
    }

    #pragma unroll
    for (int r = 0; r < RI; ++r)
        s->logitsP[hh][(g * RI + r) * L + j] = redu2(acc[r]);

    asm volatile("cp.async.wait_group 0;" ::: "memory");
    __syncthreads();

    // ---------------- Phase 2: softmax (warps 0-15, 1 row each) ------------
    if (tid < 512) {
        const int r = tid >> 5, lane = tid & 31;
        const float* lp0 = s->logitsP[0] + r * L;
        const float* lp1 = s->logitsP[1] + r * L;
        const float* mr  = s->maskS + r * L;
        float vals[8];
        float mx = -INFINITY;
        #pragma unroll
        for (int t = 0; t < 8; ++t) {
            const int jj = lane + 32 * t;
            const float lg = lp0[jj] + lp1[jj] + b2x2 + mr[jj] * (-1e9f);
            vals[t] = lg;
            mx = fmaxf(mx, lg);
        }
        #pragma unroll
        for (int m = 16; m > 0; m >>= 1)
            mx = fmaxf(mx, __shfl_xor_sync(0xffffffffu, mx, m));
        float sum = 0.f;
        #pragma unroll
        for (int t = 0; t < 8; ++t) { vals[t] = __expf(vals[t] - mx); sum += vals[t]; }
        #pragma unroll
        for (int m = 16; m > 0; m >>= 1)
            sum += __shfl_xor_sync(0xffffffffu, sum, m);
        const float inv = 1.f / sum;
        #pragma unroll
        for (int t = 0; t < 8; ++t)
            s->logitsP[0][r * L + lane + 32 * t] = vals[t] * inv;
    }
    __syncthreads();

    // aliased scratch
    float* ctxp   = s->maskS;            // 1024
    float* fp     = s->maskS + 1024;     // 1024
    float* csum   = s->maskS + 2048;     // 256
    float* hidden = s->logitsP[1];       // 2048 (partials dead after phase 2)

    // ---------------- Phase 3: ctx = attn @ v (4 j-quarters) ---------------
    {
        const int q = tid >> 8, p = tid & 255;
        const int il = p >> 4, dl = p & 15;
        const float4* arow = reinterpret_cast<const float4*>(s->logitsP[0] + il * L + q * 64);
        const float4* vrow = reinterpret_cast<const float4*>(s->vT + dl * 260 + q * 64);
        float c = 0.f;
        #pragma unroll
        for (int t = 0; t < 16; ++t) {
            const float4 a4 = arow[t];
            const float4 v4 = vrow[t];
            c = fmaf(a4.x, v4.x, c);
            c = fmaf(a4.y, v4.y, c);
            c = fmaf(a4.z, v4.z, c);
            c = fmaf(a4.w, v4.w, c);
        }
        ctxp[q * 256 + p] = c;
    }
    __syncthreads();

    // attn_out + residual + LN1 (first 256 threads)
    if (tid < 256) {
        const int il = tid >> 4, dl = tid & 15;
        csum[tid] = ctxp[tid] + ctxp[256 + tid] + ctxp[512 + tid] + ctxp[768 + tid];
        __syncwarp();
        float ao = s->bo[dl];
        #pragma unroll
        for (int e = 0; e < D; ++e)
            ao = fmaf(csum[il * D + e], s->wo[e * D + dl], ao);
        const float hval = s->xr[tid] + ao;   // RES=1
        float m = hval, sq = hval * hval;
        #pragma unroll
        for (int msk = 8; msk > 0; msk >>= 1) {
            m  += __shfl_xor_sync(0xffffffffu, m,  msk);
            sq += __shfl_xor_sync(0xffffffffu, sq, msk);
        }
        m *= (1.f / 16.f);
        const float var = sq * (1.f / 16.f) - m * m;
        s->out1[tid] = (hval - m) * rsqrtf(var + EPSV) * s->g1[dl] + s->be1[dl];
    }
    __syncthreads();

    // ---------------- Phase 4: FFN hidden (1024 threads, 2 i's each) -------
    {
        const int h = tid & 127;
        const int grp = tid >> 7;     // 0..7
        #pragma unroll
        for (int cc = 0; cc < 2; ++cc) {
            const int il = grp * 2 + cc;
            float a2 = s->f1b[h];
            #pragma unroll
            for (int d = 0; d < D; ++d)
                a2 = fmaf(s->out1[il * D + d], s->f1[d * DFF + h], a2);
            hidden[il * DFF + h] = fmaxf(a2, 0.f);
        }
    }
    __syncthreads();

    // f2 contraction (f2T, float4), 4 h-quarters
    {
        const int q = tid >> 8, p = tid & 255;
        const int il = p >> 4, dl = p & 15;
        const float4* hrow = reinterpret_cast<const float4*>(hidden + il * DFF + q * 32);
        const float4* frow = reinterpret_cast<const float4*>(s->f2T + dl * 132 + q * 32);
        float f = 0.f;
        #pragma unroll
        for (int t = 0; t < 8; ++t) {
            const float4 h4 = hrow[t];
            const float4 f4 = frow[t];
            f = fmaf(h4.x, f4.x, f);
            f = fmaf(h4.y, f4.y, f);
            f = fmaf(h4.z, f4.z, f);
            f = fmaf(h4.w, f4.w, f);
        }
        fp[q * 256 + p] = f;
    }
    __syncthreads();

    if (tid < 256) {
        const int il = tid >> 4, dl = tid & 15;
        const float f = s->f2b[dl] + fp[tid] + fp[256 + tid] + fp[512 + tid] + fp[768 + tid];
        const float hval = s->out1[tid] + f;   // RES=1
        float m = hval, sq = hval * hval;
        #pragma unroll
        for (int msk = 8; msk > 0; msk >>= 1) {
            m  += __shfl_xor_sync(0xffffffffu, m,  msk);
            sq += __shfl_xor_sync(0xffffffffu, sq, msk);
        }
        m *= (1.f / 16.f);
        const float var = sq * (1.f / 16.f) - m * m;
        const float o = (hval - m) * rsqrtf(var + EPSV) * s->g2[dl] + s->be2[dl];
        out[(size_t)(b * L + iBase + il) * D + dl] = o;
    }
}

// ---------------------------------------------------------------------------
extern "C" void kernel_launch(void* const* d_in, const int* in_sizes, int n_in,
                              void* d_out, int out_size)
{
    const float* x     = (const float*)d_in[0];
    const float* mask  = (const float*)d_in[1];
    const float* wq    = (const float*)d_in[2];
    const float* bq    = (const float*)d_in[3];
    const float* wk    = (const float*)d_in[4];
    const float* bk    = (const float*)d_in[5];
    const float* wv    = (const float*)d_in[6];
    const float* bv    = (const float*)d_in[7];
    const float* wo    = (const float*)d_in[8];
    const float* bo    = (const float*)d_in[9];
    const float* nn_w1 = (const float*)d_in[10];
    const float* nn_b1 = (const float*)d_in[11];
    const float* nn_w2 = (const float*)d_in[12];
    const float* nn_b2 = (const float*)d_in[13];
    const float* f1    = (const float*)d_in[14];
    const float* f1b   = (const float*)d_in[15];
    const float* f2    = (const float*)d_in[16];
    const float* f2b   = (const float*)d_in[17];
    const float* g1    = (const float*)d_in[18];
    const float* be1   = (const float*)d_in[19];
    const float* g2    = (const float*)d_in[20];
    const float* be2   = (const float*)d_in[21];
    float* out = (float*)d_out;

    cudaFuncSetAttribute(k_main, cudaFuncAttributeMaxDynamicSharedMemorySize,
                         (int)sizeof(Smem));

    k_precompute<<<B * L, 128>>>(x, wq, bq, wk, bk, wv, bv, nn_w1, nn_b1);
    k_main<<<B * (L / TI), 1024, sizeof(Smem)>>>(
        x, mask, wo, bo, nn_w2, nn_b2, f1, f1b, f2, f2b, g1, be1, g2, be2, out);
}